// round 8
// baseline (speedup 1.0000x reference)
#include <cuda_runtime.h>
#include <math.h>

#define KPT    133
#define PTS3   399
#define SPW    4              // samples per warp (8 lanes each)
#define SPB    16             // samples per block (4 warps)
#define RSTRIDE 408           // padded row stride: 16B-aligned, conflict-free for 12-float chunks
#define TOFF   (SPW * RSTRIDE)         // 1632
#define WFLTS  (2 * SPW * RSTRIDE)     // 3264 floats per warp slab
#define NPART  (4096 * 4)
#define RED1   32

__device__ double g_part[NPART];
__device__ double g_part2[RED1];

__device__ __forceinline__ float hsum8(float v) {
#pragma unroll
    for (int o = 4; o > 0; o >>= 1) v += __shfl_xor_sync(0xffffffffu, v, o);
    return v;
}

// Exact minimal-angle Jacobi rotation, 2 MUFU, no divisions.
__device__ __forceinline__ void jrot(float& app, float& aqq, float& apq,
                                     float& bkp, float& bkq,
                                     float& vp0, float& vq0,
                                     float& vp1, float& vq1,
                                     float& vp2, float& vq2)
{
    float a  = apq;
    float d  = aqq - app;
    float q2 = d * d + 4.f * a * a;
    float hyp = q2 * rsqrtf(fmaxf(q2, 1e-30f));          // sqrt(d^2+4a^2)
    float ch = fabsf(d) + hyp + 1e-15f;
    float sh = 2.f * a * copysignf(1.f, d);
    float w  = rsqrtf(ch * ch + sh * sh);
    float c  = ch * w;
    float s  = sh * w;
    float cc = c * c, ss = s * s, cs2a = 2.f * c * s * a;
    float napp = cc * app + ss * aqq - cs2a;
    float naqq = ss * app + cc * aqq + cs2a;
    app = napp; aqq = naqq; apq = 0.f;
    float t0 = bkp, t1 = bkq;
    bkp = c * t0 - s * t1;  bkq = s * t0 + c * t1;
    t0 = vp0; t1 = vq0; vp0 = c * t0 - s * t1; vq0 = s * t0 + c * t1;
    t0 = vp1; t1 = vq1; vp1 = c * t0 - s * t1; vq1 = s * t0 + c * t1;
    t0 = vp2; t1 = vq2; vp2 = c * t0 - s * t1; vq2 = s * t0 + c * t1;
}

#define CSWAP(la, lb, x0, x1, y0, y1, z0, z1) \
    { float _t; _t = la; la = lb; lb = _t; _t = x0; x0 = x1; x1 = _t; \
      _t = y0; y0 = y1; y1 = _t; _t = z0; z0 = z1; z1 = _t; }

__global__ void __launch_bounds__(128, 4)
k_pa(const float* __restrict__ g_outp, const float* __restrict__ g_tgtp, int n)
{
    extern __shared__ float sh[];

    const int tid  = threadIdx.x;
    const int warp = tid >> 5;
    const int lane = tid & 31;
    const int grp  = lane >> 3;          // 0..3: sample within warp
    const int q    = lane & 7;           // lane within 8-lane group

    float* wbase = sh + warp * WFLTS;    // warp-private slab

    const int warpS0 = blockIdx.x * SPB + warp * SPW;
    const int sample = warpS0 + grp;
    const bool valid = (sample < n);

    // ---------- Stage: row-wise coalesced scalar copy into 408-strided rows ----------
    if (warpS0 + SPW <= n) {
#pragma unroll
        for (int r = 0; r < SPW; ++r) {
            const float* so = g_outp + (size_t)(warpS0 + r) * PTS3;
            const float* st = g_tgtp + (size_t)(warpS0 + r) * PTS3;
            float* dor = wbase + r * RSTRIDE;
            float* dtr = wbase + TOFF + r * RSTRIDE;
#pragma unroll 4
            for (int i = lane; i < PTS3; i += 32) {
                dor[i] = so[i];
                dtr[i] = st[i];
            }
            if (lane < RSTRIDE - PTS3) {
                dor[PTS3 + lane] = 0.f;
                dtr[PTS3 + lane] = 0.f;
            }
        }
    } else if (warpS0 < n) {
        for (int i = lane; i < WFLTS; i += 32) wbase[i] = 0.f;   // rare tail path
        __syncwarp();
        int nf = (n - warpS0) * PTS3;
        const float* srcO = g_outp + (size_t)warpS0 * PTS3;
        const float* srcT = g_tgtp + (size_t)warpS0 * PTS3;
        for (int i = lane; i < nf; i += 32) {
            int r = i / PTS3, cc = i - r * PTS3;
            wbase[r * RSTRIDE + cc]        = srcO[i];
            wbase[TOFF + r * RSTRIDE + cc] = srcT[i];
        }
    }
    __syncwarp();

    const float* orow = wbase + grp * RSTRIDE;
    const float* trow = wbase + TOFF + grp * RSTRIDE;

    // ---------- Phase A: per-sample sums, 12-float chunks via LDS.128 ----------
    float s1x = 0.f, s1y = 0.f, s1z = 0.f;
    float s2x = 0.f, s2y = 0.f, s2z = 0.f;
    float tt  = 0.f;
    float c00 = 0.f, c01 = 0.f, c02 = 0.f;
    float c10 = 0.f, c11 = 0.f, c12 = 0.f;
    float c20 = 0.f, c21 = 0.f, c22 = 0.f;

#define ACC(TX, TY, TZ, OX, OY, OZ) do {                               \
        float _tx = (TX), _ty = (TY), _tz = (TZ);                      \
        float _ox = (OX), _oy = (OY), _oz = (OZ);                      \
        s2x += _ox; s2y += _oy; s2z += _oz;                            \
        s1x += _tx; s1y += _ty; s1z += _tz;                            \
        tt  += _tx * _tx + _ty * _ty + _tz * _tz;                      \
        c00 += _tx * _ox; c01 += _tx * _oy; c02 += _tx * _oz;          \
        c10 += _ty * _ox; c11 += _ty * _oy; c12 += _ty * _oz;          \
        c20 += _tz * _ox; c21 += _tz * _oy; c22 += _tz * _oz;          \
    } while (0)

#pragma unroll 5
    for (int c = q; c < RSTRIDE / 12; c += 8) {       // 34 chunks of 4 points
        const float4* o4 = (const float4*)(orow + 12 * c);
        const float4* t4 = (const float4*)(trow + 12 * c);
        float4 oa = o4[0], ob = o4[1], oc = o4[2];
        float4 ta = t4[0], tb = t4[1], tc = t4[2];
        ACC(ta.x, ta.y, ta.z, oa.x, oa.y, oa.z);
        ACC(ta.w, tb.x, tb.y, oa.w, ob.x, ob.y);
        ACC(tb.z, tb.w, tc.x, ob.z, ob.w, oc.x);
        ACC(tc.y, tc.z, tc.w, oc.y, oc.z, oc.w);
    }
#undef ACC

    s1x = hsum8(s1x); s1y = hsum8(s1y); s1z = hsum8(s1z);
    s2x = hsum8(s2x); s2y = hsum8(s2y); s2z = hsum8(s2z);
    tt  = hsum8(tt);
    c00 = hsum8(c00); c01 = hsum8(c01); c02 = hsum8(c02);
    c10 = hsum8(c10); c11 = hsum8(c11); c12 = hsum8(c12);
    c20 = hsum8(c20); c21 = hsum8(c21); c22 = hsum8(c22);

    const float invK = 1.0f / (float)KPT;
    float m1x = s1x * invK, m1y = s1y * invK, m1z = s1z * invK;
    float m2x = s2x * invK, m2y = s2y * invK, m2z = s2z * invK;

    float k00 = c00 - s1x * m2x, k01 = c01 - s1x * m2y, k02 = c02 - s1x * m2z;
    float k10 = c10 - s1y * m2x, k11 = c11 - s1y * m2y, k12 = c12 - s1y * m2z;
    float k20 = c20 - s1z * m2x, k21 = c21 - s1z * m2y, k22 = c22 - s1z * m2z;
    float var1 = tt - (s1x * m1x + s1y * m1y + s1z * m1z);

    // ---------- Phase B: 3x3 SVD, redundant per 8-lane group ----------
    float b00 = k00 * k00 + k10 * k10 + k20 * k20;
    float b01 = k00 * k01 + k10 * k11 + k20 * k21;
    float b02 = k00 * k02 + k10 * k12 + k20 * k22;
    float b11 = k01 * k01 + k11 * k11 + k21 * k21;
    float b12 = k01 * k02 + k11 * k12 + k21 * k22;
    float b22 = k02 * k02 + k12 * k12 + k22 * k22;

    float v00 = 1.f, v01 = 0.f, v02 = 0.f;
    float v10 = 0.f, v11 = 1.f, v12 = 0.f;
    float v20 = 0.f, v21 = 0.f, v22 = 1.f;

#pragma unroll
    for (int sweep = 0; sweep < 4; ++sweep) {
        jrot(b00, b11, b01, b02, b12, v00, v01, v10, v11, v20, v21);
        jrot(b00, b22, b02, b01, b12, v00, v02, v10, v12, v20, v22);
        jrot(b11, b22, b12, b01, b02, v01, v02, v11, v12, v21, v22);
    }

    if (b00 < b11) CSWAP(b00, b11, v00, v01, v10, v11, v20, v21);
    if (b00 < b22) CSWAP(b00, b22, v00, v02, v10, v12, v20, v22);
    if (b11 < b22) CSWAP(b11, b22, v01, v02, v11, v12, v21, v22);

    float rs0 = rsqrtf(fmaxf(b00, 1e-30f));
    float rs1 = rsqrtf(fmaxf(b11, 1e-30f));
    float rs2 = rsqrtf(fmaxf(b22, 1e-30f));
    float s0 = fmaxf(b00, 0.f) * rs0;
    float s1 = fmaxf(b11, 0.f) * rs1;
    float s2 = fmaxf(b22, 0.f) * rs2;

    float a0 = k00 * v00 + k01 * v10 + k02 * v20;
    float a1 = k10 * v00 + k11 * v10 + k12 * v20;
    float a2 = k20 * v00 + k21 * v10 + k22 * v20;
    float u0x = a0 * rs0, u0y = a1 * rs0, u0z = a2 * rs0;

    float e0 = k00 * v01 + k01 * v11 + k02 * v21;
    float e1 = k10 * v01 + k11 * v11 + k12 * v21;
    float e2 = k20 * v01 + k21 * v11 + k22 * v21;
    float u1x = e0 * rs1, u1y = e1 * rs1, u1z = e2 * rs1;

    float g0 = k00 * v02 + k01 * v12 + k02 * v22;
    float g1 = k10 * v02 + k11 * v12 + k12 * v22;
    float g2 = k20 * v02 + k21 * v12 + k22 * v22;
    float wx = u0y * u1z - u0z * u1y;
    float wy = u0z * u1x - u0x * u1z;
    float wz = u0x * u1y - u0y * u1x;
    float wn = rsqrtf(fmaxf(wx * wx + wy * wy + wz * wz, 1e-30f));
    wx *= wn; wy *= wn; wz *= wn;
    float sgn = (g0 * wx + g1 * wy + g2 * wz) >= 0.f ? 1.f : -1.f;
    float u2x = sgn * wx, u2y = sgn * wy, u2z = sgn * wz;

    float detK = k00 * (k11 * k22 - k12 * k21)
               - k01 * (k10 * k22 - k12 * k20)
               + k02 * (k10 * k21 - k11 * k20);
    float z = (detK >= 0.f) ? 1.f : -1.f;

    float scale = __fdividef(s0 + s1 + z * s2, var1);

    float r00 = scale * (v00 * u0x + v01 * u1x + z * v02 * u2x);
    float r01 = scale * (v00 * u0y + v01 * u1y + z * v02 * u2y);
    float r02 = scale * (v00 * u0z + v01 * u1z + z * v02 * u2z);
    float r10 = scale * (v10 * u0x + v11 * u1x + z * v12 * u2x);
    float r11 = scale * (v10 * u0y + v11 * u1y + z * v12 * u2y);
    float r12 = scale * (v10 * u0z + v11 * u1z + z * v12 * u2z);
    float r20 = scale * (v20 * u0x + v21 * u1x + z * v22 * u2x);
    float r21 = scale * (v20 * u0y + v21 * u1y + z * v22 * u2y);
    float r22 = scale * (v20 * u0z + v21 * u1z + z * v22 * u2z);

    float tr_x = m2x - (r00 * m1x + r01 * m1y + r02 * m1z);
    float tr_y = m2y - (r10 * m1x + r11 * m1y + r12 * m1z);
    float tr_z = m2z - (r20 * m1x + r21 * m1y + r22 * m1z);

    // ---------- Phase C: residual norms, same chunked LDS.128 ----------
    float lsum = 0.f;

#define RES(TX, TY, TZ, OX, OY, OZ) do {                               \
        float _tx = (TX), _ty = (TY), _tz = (TZ);                      \
        float ax = tr_x + r00 * _tx + r01 * _ty + r02 * _tz;           \
        float ay = tr_y + r10 * _tx + r11 * _ty + r12 * _tz;           \
        float az = tr_z + r20 * _tx + r21 * _ty + r22 * _tz;           \
        float dx = (OX) - ax;                                          \
        float dy = (OY) - ay;                                          \
        float dz = (OZ) - az;                                          \
        float d2 = fmaxf(dx * dx + dy * dy + dz * dz, 1e-30f);         \
        lsum += d2 * rsqrtf(d2);                                       \
    } while (0)

#pragma unroll 5
    for (int c = q; c < RSTRIDE / 12; c += 8) {
        const float4* o4 = (const float4*)(orow + 12 * c);
        const float4* t4 = (const float4*)(trow + 12 * c);
        float4 oa = o4[0], ob = o4[1], oc = o4[2];
        float4 ta = t4[0], tb = t4[1], tc = t4[2];
        RES(ta.x, ta.y, ta.z, oa.x, oa.y, oa.z);
        RES(ta.w, tb.x, tb.y, oa.w, ob.x, ob.y);
        RES(tb.z, tb.w, tc.x, ob.z, ob.w, oc.x);
        RES(tc.y, tc.z, tc.w, oc.y, oc.z, oc.w);
    }
#undef RES

    lsum = hsum8(lsum);
    // remove the 3 zero-pad points (each contributed exactly |tr| via the same formula)
    {
        float tp2 = fmaxf(tr_x * tr_x + tr_y * tr_y + tr_z * tr_z, 1e-30f);
        lsum -= 3.f * (tp2 * rsqrtf(tp2));
    }
    if (!valid) lsum = 0.f;

    lsum += __shfl_xor_sync(0xffffffffu, lsum, 8);
    lsum += __shfl_xor_sync(0xffffffffu, lsum, 16);
    if (lane == 0)
        g_part[(size_t)blockIdx.x * 4 + warp] = (double)lsum;
}

__global__ void k_reduce1(int nparts)
{
    __shared__ double shd[8];
    int per = (nparts + RED1 - 1) / RED1;
    int lo  = blockIdx.x * per;
    int hi  = min(lo + per, nparts);
    double s = 0.0;
    for (int i = lo + threadIdx.x; i < hi; i += blockDim.x) s += g_part[i];
#pragma unroll
    for (int o = 16; o > 0; o >>= 1) s += __shfl_xor_sync(0xffffffffu, s, o);
    int wi = threadIdx.x >> 5, lane = threadIdx.x & 31;
    if (lane == 0) shd[wi] = s;
    __syncthreads();
    if (threadIdx.x < 32) {
        int nw = blockDim.x >> 5;
        double v = (threadIdx.x < nw) ? shd[threadIdx.x] : 0.0;
#pragma unroll
        for (int o = 4; o > 0; o >>= 1) v += __shfl_xor_sync(0xffffffffu, v, o);
        if (threadIdx.x == 0) g_part2[blockIdx.x] = v;
    }
}

__global__ void k_reduce2(float* __restrict__ out, double inv_cnt)
{
    double v = (threadIdx.x < RED1) ? g_part2[threadIdx.x] : 0.0;
#pragma unroll
    for (int o = 16; o > 0; o >>= 1) v += __shfl_xor_sync(0xffffffffu, v, o);
    if (threadIdx.x == 0) out[0] = (float)(v * inv_cnt);
}

extern "C" void kernel_launch(void* const* d_in, const int* in_sizes, int n_in,
                              void* d_out, int out_size)
{
    const float* g_output = (const float*)d_in[0];
    const float* g_target = (const float*)d_in[1];
    int n = in_sizes[0] / PTS3;

    size_t shbytes = (size_t)4 * WFLTS * sizeof(float);   // 52224 B
    cudaFuncSetAttribute(k_pa, cudaFuncAttributeMaxDynamicSharedMemorySize, (int)shbytes);

    int blocks = (n + SPB - 1) / SPB;
    k_pa<<<blocks, 128, shbytes>>>(g_output, g_target, n);
    k_reduce1<<<RED1, 256>>>(blocks * 4);
    double inv_cnt = 1.0 / ((double)n * (double)KPT);
    k_reduce2<<<1, 32>>>((float*)d_out, inv_cnt);
}

// round 10
// speedup vs baseline: 1.4700x; 1.4700x over previous
#include <cuda_runtime.h>
#include <math.h>

#define KPT    133
#define PTS3   399
#define SPW    2              // samples per warp (16 lanes each)
#define SPB    8              // samples per block (4 warps x 2)
#define TOFF   (SPW * PTS3)   // 798: offset of target plane in warp slab
#define WFLTS  (2 * SPW * PTS3)   // 1596 floats per warp slab
#define NPART  (8192 * 4)
#define RED1   32

__device__ double g_part[NPART];
__device__ double g_part2[RED1];

// butterfly over a 16-lane group (offsets 8..1); groups stay independent
__device__ __forceinline__ float hsum16(float v) {
#pragma unroll
    for (int o = 8; o > 0; o >>= 1) v += __shfl_xor_sync(0xffffffffu, v, o);
    return v;
}

// Exact minimal-angle Jacobi rotation, 2 MUFU, no divisions.
__device__ __forceinline__ void jrot(float& app, float& aqq, float& apq,
                                     float& bkp, float& bkq,
                                     float& vp0, float& vq0,
                                     float& vp1, float& vq1,
                                     float& vp2, float& vq2)
{
    float a  = apq;
    float d  = aqq - app;
    float q2 = d * d + 4.f * a * a;
    float hyp = q2 * rsqrtf(fmaxf(q2, 1e-30f));          // sqrt(d^2+4a^2)
    float ch = fabsf(d) + hyp + 1e-15f;
    float sh = 2.f * a * copysignf(1.f, d);
    float w  = rsqrtf(ch * ch + sh * sh);
    float c  = ch * w;
    float s  = sh * w;
    float cc = c * c, ss = s * s, cs2a = 2.f * c * s * a;
    float napp = cc * app + ss * aqq - cs2a;
    float naqq = ss * app + cc * aqq + cs2a;
    app = napp; aqq = naqq; apq = 0.f;
    float t0 = bkp, t1 = bkq;
    bkp = c * t0 - s * t1;  bkq = s * t0 + c * t1;
    t0 = vp0; t1 = vq0; vp0 = c * t0 - s * t1; vq0 = s * t0 + c * t1;
    t0 = vp1; t1 = vq1; vp1 = c * t0 - s * t1; vq1 = s * t0 + c * t1;
    t0 = vp2; t1 = vq2; vp2 = c * t0 - s * t1; vq2 = s * t0 + c * t1;
}

#define CSWAP(la, lb, x0, x1, y0, y1, z0, z1) \
    { float _t; _t = la; la = lb; lb = _t; _t = x0; x0 = x1; x1 = _t; \
      _t = y0; y0 = y1; y1 = _t; _t = z0; z0 = z1; z1 = _t; }

__global__ void __launch_bounds__(128, 7)
k_pa(const float* __restrict__ g_outp, const float* __restrict__ g_tgtp, int n)
{
    extern __shared__ float sh[];

    const int tid  = threadIdx.x;
    const int warp = tid >> 5;
    const int lane = tid & 31;
    const int grp  = lane >> 4;          // 0..1: sample within warp
    const int q    = lane & 15;          // lane within 16-lane group

    float* wbase = sh + warp * WFLTS;    // warp-private slab: [o 2x399][t 2x399]

    const int warpS0 = blockIdx.x * SPB + warp * SPW;
    const int sample = warpS0 + grp;
    const bool valid = (sample < n);

    // ---------- Stage: warp-private float2 copy (slab base is 8B-aligned) ----------
    if (warpS0 + SPW <= n) {
        const float2* srcO = (const float2*)(g_outp + (size_t)warpS0 * PTS3);
        const float2* srcT = (const float2*)(g_tgtp + (size_t)warpS0 * PTS3);
        float2* dstO = (float2*)wbase;
        float2* dstT = (float2*)(wbase + TOFF);
#pragma unroll 4
        for (int i = lane; i < (SPW * PTS3) / 2; i += 32) {   // 399 float2 per array
            dstO[i] = srcO[i];
            dstT[i] = srcT[i];
        }
    } else if (warpS0 < n) {
        int nf = (n - warpS0) * PTS3;    // guarded scalar tail copy
        const float* srcO = g_outp + (size_t)warpS0 * PTS3;
        const float* srcT = g_tgtp + (size_t)warpS0 * PTS3;
        for (int i = lane; i < nf; i += 32) {
            wbase[i]        = srcO[i];
            wbase[TOFF + i] = srcT[i];
        }
    }
    __syncwarp();

    const float* po = wbase + grp * PTS3;
    const float* pt = wbase + TOFF + grp * PTS3;

    // ---------- Phase A: per-sample sums (16 lanes/sample, LDS) ----------
    float s1x = 0.f, s1y = 0.f, s1z = 0.f;
    float s2x = 0.f, s2y = 0.f, s2z = 0.f;
    float tt  = 0.f;
    float c00 = 0.f, c01 = 0.f, c02 = 0.f;
    float c10 = 0.f, c11 = 0.f, c12 = 0.f;
    float c20 = 0.f, c21 = 0.f, c22 = 0.f;

#pragma unroll 3
    for (int j = q; j < KPT; j += 16) {
        float ox = po[3 * j + 0], oy = po[3 * j + 1], oz = po[3 * j + 2];
        float tx = pt[3 * j + 0], ty = pt[3 * j + 1], tz = pt[3 * j + 2];
        s2x += ox; s2y += oy; s2z += oz;
        s1x += tx; s1y += ty; s1z += tz;
        tt  += tx * tx + ty * ty + tz * tz;
        c00 += tx * ox; c01 += tx * oy; c02 += tx * oz;
        c10 += ty * ox; c11 += ty * oy; c12 += ty * oz;
        c20 += tz * ox; c21 += tz * oy; c22 += tz * oz;
    }

    s1x = hsum16(s1x); s1y = hsum16(s1y); s1z = hsum16(s1z);
    s2x = hsum16(s2x); s2y = hsum16(s2y); s2z = hsum16(s2z);
    tt  = hsum16(tt);
    c00 = hsum16(c00); c01 = hsum16(c01); c02 = hsum16(c02);
    c10 = hsum16(c10); c11 = hsum16(c11); c12 = hsum16(c12);
    c20 = hsum16(c20); c21 = hsum16(c21); c22 = hsum16(c22);

    const float invK = 1.0f / (float)KPT;
    float m1x = s1x * invK, m1y = s1y * invK, m1z = s1z * invK;
    float m2x = s2x * invK, m2y = s2y * invK, m2z = s2z * invK;

    float k00 = c00 - s1x * m2x, k01 = c01 - s1x * m2y, k02 = c02 - s1x * m2z;
    float k10 = c10 - s1y * m2x, k11 = c11 - s1y * m2y, k12 = c12 - s1y * m2z;
    float k20 = c20 - s1z * m2x, k21 = c21 - s1z * m2y, k22 = c22 - s1z * m2z;
    float var1 = tt - (s1x * m1x + s1y * m1y + s1z * m1z);

    // ---------- Phase B: 3x3 SVD, redundant per 16-lane group ----------
    float b00 = k00 * k00 + k10 * k10 + k20 * k20;
    float b01 = k00 * k01 + k10 * k11 + k20 * k21;
    float b02 = k00 * k02 + k10 * k12 + k20 * k22;
    float b11 = k01 * k01 + k11 * k11 + k21 * k21;
    float b12 = k01 * k02 + k11 * k12 + k21 * k22;
    float b22 = k02 * k02 + k12 * k12 + k22 * k22;

    float v00 = 1.f, v01 = 0.f, v02 = 0.f;
    float v10 = 0.f, v11 = 1.f, v12 = 0.f;
    float v20 = 0.f, v21 = 0.f, v22 = 1.f;

#pragma unroll
    for (int sweep = 0; sweep < 4; ++sweep) {
        jrot(b00, b11, b01, b02, b12, v00, v01, v10, v11, v20, v21);
        jrot(b00, b22, b02, b01, b12, v00, v02, v10, v12, v20, v22);
        jrot(b11, b22, b12, b01, b02, v01, v02, v11, v12, v21, v22);
    }

    if (b00 < b11) CSWAP(b00, b11, v00, v01, v10, v11, v20, v21);
    if (b00 < b22) CSWAP(b00, b22, v00, v02, v10, v12, v20, v22);
    if (b11 < b22) CSWAP(b11, b22, v01, v02, v11, v12, v21, v22);

    float rs0 = rsqrtf(fmaxf(b00, 1e-30f));
    float rs1 = rsqrtf(fmaxf(b11, 1e-30f));
    float rs2 = rsqrtf(fmaxf(b22, 1e-30f));
    float s0 = fmaxf(b00, 0.f) * rs0;
    float s1 = fmaxf(b11, 0.f) * rs1;
    float s2 = fmaxf(b22, 0.f) * rs2;

    float a0 = k00 * v00 + k01 * v10 + k02 * v20;
    float a1 = k10 * v00 + k11 * v10 + k12 * v20;
    float a2 = k20 * v00 + k21 * v10 + k22 * v20;
    float u0x = a0 * rs0, u0y = a1 * rs0, u0z = a2 * rs0;

    float e0 = k00 * v01 + k01 * v11 + k02 * v21;
    float e1 = k10 * v01 + k11 * v11 + k12 * v21;
    float e2 = k20 * v01 + k21 * v11 + k22 * v21;
    float u1x = e0 * rs1, u1y = e1 * rs1, u1z = e2 * rs1;

    float g0 = k00 * v02 + k01 * v12 + k02 * v22;
    float g1 = k10 * v02 + k11 * v12 + k12 * v22;
    float g2 = k20 * v02 + k21 * v12 + k22 * v22;
    float wx = u0y * u1z - u0z * u1y;
    float wy = u0z * u1x - u0x * u1z;
    float wz = u0x * u1y - u0y * u1x;
    float wn = rsqrtf(fmaxf(wx * wx + wy * wy + wz * wz, 1e-30f));
    wx *= wn; wy *= wn; wz *= wn;
    float sgn = (g0 * wx + g1 * wy + g2 * wz) >= 0.f ? 1.f : -1.f;
    float u2x = sgn * wx, u2y = sgn * wy, u2z = sgn * wz;

    float detK = k00 * (k11 * k22 - k12 * k21)
               - k01 * (k10 * k22 - k12 * k20)
               + k02 * (k10 * k21 - k11 * k20);
    float z = (detK >= 0.f) ? 1.f : -1.f;

    float scale = __fdividef(s0 + s1 + z * s2, var1);

    float r00 = scale * (v00 * u0x + v01 * u1x + z * v02 * u2x);
    float r01 = scale * (v00 * u0y + v01 * u1y + z * v02 * u2y);
    float r02 = scale * (v00 * u0z + v01 * u1z + z * v02 * u2z);
    float r10 = scale * (v10 * u0x + v11 * u1x + z * v12 * u2x);
    float r11 = scale * (v10 * u0y + v11 * u1y + z * v12 * u2y);
    float r12 = scale * (v10 * u0z + v11 * u1z + z * v12 * u2z);
    float r20 = scale * (v20 * u0x + v21 * u1x + z * v22 * u2x);
    float r21 = scale * (v20 * u0y + v21 * u1y + z * v22 * u2y);
    float r22 = scale * (v20 * u0z + v21 * u1z + z * v22 * u2z);

    float tr_x = m2x - (r00 * m1x + r01 * m1y + r02 * m1z);
    float tr_y = m2y - (r10 * m1x + r11 * m1y + r12 * m1z);
    float tr_z = m2z - (r20 * m1x + r21 * m1y + r22 * m1z);

    // ---------- Phase C: residual norms (LDS re-read) ----------
    float lsum = 0.f;
#pragma unroll 3
    for (int j = q; j < KPT; j += 16) {
        float tx = pt[3 * j + 0], ty = pt[3 * j + 1], tz = pt[3 * j + 2];
        float ax = tr_x + r00 * tx + r01 * ty + r02 * tz;
        float ay = tr_y + r10 * tx + r11 * ty + r12 * tz;
        float az = tr_z + r20 * tx + r21 * ty + r22 * tz;
        float dx = po[3 * j + 0] - ax;
        float dy = po[3 * j + 1] - ay;
        float dz = po[3 * j + 2] - az;
        float d2 = fmaxf(dx * dx + dy * dy + dz * dz, 1e-30f);
        lsum += d2 * rsqrtf(d2);
    }
    lsum = hsum16(lsum);
    if (!valid) lsum = 0.f;

    // combine the 2 groups; lane 0 writes one double per warp
    lsum += __shfl_xor_sync(0xffffffffu, lsum, 16);
    if (lane == 0)
        g_part[(size_t)blockIdx.x * 4 + warp] = (double)lsum;
}

__global__ void k_reduce1(int nparts)
{
    __shared__ double shd[8];
    int per = (nparts + RED1 - 1) / RED1;
    int lo  = blockIdx.x * per;
    int hi  = min(lo + per, nparts);
    double s = 0.0;
    for (int i = lo + threadIdx.x; i < hi; i += blockDim.x) s += g_part[i];
#pragma unroll
    for (int o = 16; o > 0; o >>= 1) s += __shfl_xor_sync(0xffffffffu, s, o);
    int wi = threadIdx.x >> 5, lane = threadIdx.x & 31;
    if (lane == 0) shd[wi] = s;
    __syncthreads();
    if (threadIdx.x < 32) {
        int nw = blockDim.x >> 5;
        double v = (threadIdx.x < nw) ? shd[threadIdx.x] : 0.0;
#pragma unroll
        for (int o = 4; o > 0; o >>= 1) v += __shfl_xor_sync(0xffffffffu, v, o);
        if (threadIdx.x == 0) g_part2[blockIdx.x] = v;
    }
}

__global__ void k_reduce2(float* __restrict__ out, double inv_cnt)
{
    double v = (threadIdx.x < RED1) ? g_part2[threadIdx.x] : 0.0;
#pragma unroll
    for (int o = 16; o > 0; o >>= 1) v += __shfl_xor_sync(0xffffffffu, v, o);
    if (threadIdx.x == 0) out[0] = (float)(v * inv_cnt);
}

extern "C" void kernel_launch(void* const* d_in, const int* in_sizes, int n_in,
                              void* d_out, int out_size)
{
    const float* g_output = (const float*)d_in[0];
    const float* g_target = (const float*)d_in[1];
    int n = in_sizes[0] / PTS3;

    size_t shbytes = (size_t)4 * WFLTS * sizeof(float);   // 25536 B per block
    cudaFuncSetAttribute(k_pa, cudaFuncAttributeMaxDynamicSharedMemorySize, (int)shbytes);

    int blocks = (n + SPB - 1) / SPB;
    k_pa<<<blocks, 128, shbytes>>>(g_output, g_target, n);
    k_reduce1<<<RED1, 256>>>(blocks * 4);
    double inv_cnt = 1.0 / ((double)n * (double)KPT);
    k_reduce2<<<1, 32>>>((float*)d_out, inv_cnt);
}

// round 11
// speedup vs baseline: 1.5894x; 1.0812x over previous
#include <cuda_runtime.h>
#include <math.h>

#define KPT    133
#define PTS3   399
#define SPW    2              // samples per warp (16 lanes each)
#define SPB    8              // samples per block (4 warps x 2)
#define TOFF   (SPW * PTS3)   // 798
#define WFLTS  (2 * SPW * PTS3)   // 1596 floats per warp slab
#define NPART  (8192 * 4)
#define RED1   32

__device__ double g_part[NPART];
__device__ double g_part2[RED1];

// Exact minimal-angle Jacobi rotation, 2 MUFU, no divisions.
__device__ __forceinline__ void jrot(float& app, float& aqq, float& apq,
                                     float& bkp, float& bkq,
                                     float& vp0, float& vq0,
                                     float& vp1, float& vq1,
                                     float& vp2, float& vq2)
{
    float a  = apq;
    float d  = aqq - app;
    float q2 = d * d + 4.f * a * a;
    float hyp = q2 * rsqrtf(fmaxf(q2, 1e-30f));          // sqrt(d^2+4a^2)
    float ch = fabsf(d) + hyp + 1e-15f;
    float sh = 2.f * a * copysignf(1.f, d);
    float w  = rsqrtf(ch * ch + sh * sh);
    float c  = ch * w;
    float s  = sh * w;
    float cc = c * c, ss = s * s, cs2a = 2.f * c * s * a;
    float napp = cc * app + ss * aqq - cs2a;
    float naqq = ss * app + cc * aqq + cs2a;
    app = napp; aqq = naqq; apq = 0.f;
    float t0 = bkp, t1 = bkq;
    bkp = c * t0 - s * t1;  bkq = s * t0 + c * t1;
    t0 = vp0; t1 = vq0; vp0 = c * t0 - s * t1; vq0 = s * t0 + c * t1;
    t0 = vp1; t1 = vq1; vp1 = c * t0 - s * t1; vq1 = s * t0 + c * t1;
    t0 = vp2; t1 = vq2; vp2 = c * t0 - s * t1; vq2 = s * t0 + c * t1;
}

#define CSWAP(la, lb, x0, x1, y0, y1, z0, z1) \
    { float _t; _t = la; la = lb; lb = _t; _t = x0; x0 = x1; x1 = _t; \
      _t = y0; y0 = y1; y1 = _t; _t = z0; z0 = z1; z1 = _t; }

__global__ void __launch_bounds__(128, 7)
k_pa(const float* __restrict__ g_outp, const float* __restrict__ g_tgtp, int n)
{
    extern __shared__ float sh[];

    const int tid  = threadIdx.x;
    const int warp = tid >> 5;
    const int lane = tid & 31;
    const int grp  = lane >> 4;          // 0..1: sample within warp
    const int q    = lane & 15;          // lane within 16-lane group

    float* wbase = sh + warp * WFLTS;    // warp-private slab: [o 2x399][t 2x399]

    const int warpS0 = blockIdx.x * SPB + warp * SPW;
    const int sample = warpS0 + grp;
    const bool valid = (sample < n);

    // ---------- Stage: warp-private float2 copy ----------
    if (warpS0 + SPW <= n) {
        const float2* srcO = (const float2*)(g_outp + (size_t)warpS0 * PTS3);
        const float2* srcT = (const float2*)(g_tgtp + (size_t)warpS0 * PTS3);
        float2* dstO = (float2*)wbase;
        float2* dstT = (float2*)(wbase + TOFF);
#pragma unroll 4
        for (int i = lane; i < (SPW * PTS3) / 2; i += 32) {
            dstO[i] = srcO[i];
            dstT[i] = srcT[i];
        }
    } else if (warpS0 < n) {
        int nf = (n - warpS0) * PTS3;
        const float* srcO = g_outp + (size_t)warpS0 * PTS3;
        const float* srcT = g_tgtp + (size_t)warpS0 * PTS3;
        for (int i = lane; i < nf; i += 32) {
            wbase[i]        = srcO[i];
            wbase[TOFF + i] = srcT[i];
        }
    }
    __syncwarp();

    const float* po = wbase + grp * PTS3;
    const float* pt = wbase + TOFF + grp * PTS3;

    // ---------- Phase A: per-sample sums (16 lanes/sample, LDS) ----------
    // v[] layout: 0..2 s1 (sum t), 3..5 s2 (sum o), 6 tt, 7..15 c (t_a*o_b)
    float v[16];
#pragma unroll
    for (int i = 0; i < 16; ++i) v[i] = 0.f;

#define ACCJ(J) do {                                                     \
        int _j = (J);                                                    \
        float ox = po[3 * _j + 0], oy = po[3 * _j + 1], oz = po[3 * _j + 2]; \
        float tx = pt[3 * _j + 0], ty = pt[3 * _j + 1], tz = pt[3 * _j + 2]; \
        v[0] += tx; v[1] += ty; v[2] += tz;                              \
        v[3] += ox; v[4] += oy; v[5] += oz;                              \
        v[6] += tx * tx + ty * ty + tz * tz;                             \
        v[7]  += tx * ox; v[8]  += tx * oy; v[9]  += tx * oz;            \
        v[10] += ty * ox; v[11] += ty * oy; v[12] += ty * oz;            \
        v[13] += ty * oz * 0.f + tz * ox; v[14] += tz * oy; v[15] += tz * oz; \
    } while (0)

#pragma unroll 4
    for (int k = 0; k < 8; ++k) ACCJ(q + 16 * k);     // j <= 127 < 133 always valid
    if (q < KPT - 128) ACCJ(q + 128);                 // predicated tail (q < 5)
#undef ACCJ

    // ---------- Distributed butterfly reduction over the 16-lane group ----------
    // After stage of offset o: low-half keeps quantities [0..m/2), high-half [m/2..m).
    // Final: lane q holds fully-reduced quantity q of its group.
    {
#pragma unroll
        for (int off = 8, m = 16; off > 0; off >>= 1, m >>= 1) {
#pragma unroll
            for (int i = 0; i < 8; ++i) {
                if (i < (m >> 1)) {
                    float send = (q & off) ? v[i] : v[i + (m >> 1)];
                    float recv = __shfl_xor_sync(0xffffffffu, send, off);
                    v[i] = ((q & off) ? v[i + (m >> 1)] : v[i]) + recv;
                }
            }
        }
    }
    // broadcast: a[i] = reduced quantity i for this group
    float a_[16];
    {
        int base = lane & 16;
#pragma unroll
        for (int i = 0; i < 16; ++i)
            a_[i] = __shfl_sync(0xffffffffu, v[0], base + i);
    }
    float s1x = a_[0], s1y = a_[1], s1z = a_[2];
    float s2x = a_[3], s2y = a_[4], s2z = a_[5];
    float tt  = a_[6];
    float c00 = a_[7],  c01 = a_[8],  c02 = a_[9];
    float c10 = a_[10], c11 = a_[11], c12 = a_[12];
    float c20 = a_[13], c21 = a_[14], c22 = a_[15];

    const float invK = 1.0f / (float)KPT;
    float m1x = s1x * invK, m1y = s1y * invK, m1z = s1z * invK;
    float m2x = s2x * invK, m2y = s2y * invK, m2z = s2z * invK;

    float k00 = c00 - s1x * m2x, k01 = c01 - s1x * m2y, k02 = c02 - s1x * m2z;
    float k10 = c10 - s1y * m2x, k11 = c11 - s1y * m2y, k12 = c12 - s1y * m2z;
    float k20 = c20 - s1z * m2x, k21 = c21 - s1z * m2y, k22 = c22 - s1z * m2z;
    float var1 = tt - (s1x * m1x + s1y * m1y + s1z * m1z);

    // ---------- Phase B: 3x3 SVD (3 sweeps), redundant per 16-lane group ----------
    float b00 = k00 * k00 + k10 * k10 + k20 * k20;
    float b01 = k00 * k01 + k10 * k11 + k20 * k21;
    float b02 = k00 * k02 + k10 * k12 + k20 * k22;
    float b11 = k01 * k01 + k11 * k11 + k21 * k21;
    float b12 = k01 * k02 + k11 * k12 + k21 * k22;
    float b22 = k02 * k02 + k12 * k12 + k22 * k22;

    float v00 = 1.f, v01 = 0.f, v02 = 0.f;
    float v10 = 0.f, v11 = 1.f, v12 = 0.f;
    float v20 = 0.f, v21 = 0.f, v22 = 1.f;

#pragma unroll
    for (int sweep = 0; sweep < 3; ++sweep) {
        jrot(b00, b11, b01, b02, b12, v00, v01, v10, v11, v20, v21);
        jrot(b00, b22, b02, b01, b12, v00, v02, v10, v12, v20, v22);
        jrot(b11, b22, b12, b01, b02, v01, v02, v11, v12, v21, v22);
    }

    if (b00 < b11) CSWAP(b00, b11, v00, v01, v10, v11, v20, v21);
    if (b00 < b22) CSWAP(b00, b22, v00, v02, v10, v12, v20, v22);
    if (b11 < b22) CSWAP(b11, b22, v01, v02, v11, v12, v21, v22);

    float rs0 = rsqrtf(fmaxf(b00, 1e-30f));
    float rs1 = rsqrtf(fmaxf(b11, 1e-30f));
    float rs2 = rsqrtf(fmaxf(b22, 1e-30f));
    float s0 = fmaxf(b00, 0.f) * rs0;
    float s1 = fmaxf(b11, 0.f) * rs1;
    float s2 = fmaxf(b22, 0.f) * rs2;

    float a0 = k00 * v00 + k01 * v10 + k02 * v20;
    float a1 = k10 * v00 + k11 * v10 + k12 * v20;
    float a2 = k20 * v00 + k21 * v10 + k22 * v20;
    float u0x = a0 * rs0, u0y = a1 * rs0, u0z = a2 * rs0;

    float e0 = k00 * v01 + k01 * v11 + k02 * v21;
    float e1 = k10 * v01 + k11 * v11 + k12 * v21;
    float e2 = k20 * v01 + k21 * v11 + k22 * v21;
    float u1x = e0 * rs1, u1y = e1 * rs1, u1z = e2 * rs1;

    float g0 = k00 * v02 + k01 * v12 + k02 * v22;
    float g1 = k10 * v02 + k11 * v12 + k12 * v22;
    float g2 = k20 * v02 + k21 * v12 + k22 * v22;
    float wx = u0y * u1z - u0z * u1y;
    float wy = u0z * u1x - u0x * u1z;
    float wz = u0x * u1y - u0y * u1x;
    float wn = rsqrtf(fmaxf(wx * wx + wy * wy + wz * wz, 1e-30f));
    wx *= wn; wy *= wn; wz *= wn;
    float sgn = (g0 * wx + g1 * wy + g2 * wz) >= 0.f ? 1.f : -1.f;
    float u2x = sgn * wx, u2y = sgn * wy, u2z = sgn * wz;

    float detK = k00 * (k11 * k22 - k12 * k21)
               - k01 * (k10 * k22 - k12 * k20)
               + k02 * (k10 * k21 - k11 * k20);
    float z = (detK >= 0.f) ? 1.f : -1.f;

    float scale = __fdividef(s0 + s1 + z * s2, var1);

    float r00 = scale * (v00 * u0x + v01 * u1x + z * v02 * u2x);
    float r01 = scale * (v00 * u0y + v01 * u1y + z * v02 * u2y);
    float r02 = scale * (v00 * u0z + v01 * u1z + z * v02 * u2z);
    float r10 = scale * (v10 * u0x + v11 * u1x + z * v12 * u2x);
    float r11 = scale * (v10 * u0y + v11 * u1y + z * v12 * u2y);
    float r12 = scale * (v10 * u0z + v11 * u1z + z * v12 * u2z);
    float r20 = scale * (v20 * u0x + v21 * u1x + z * v22 * u2x);
    float r21 = scale * (v20 * u0y + v21 * u1y + z * v22 * u2y);
    float r22 = scale * (v20 * u0z + v21 * u1z + z * v22 * u2z);

    float tr_x = m2x - (r00 * m1x + r01 * m1y + r02 * m1z);
    float tr_y = m2y - (r10 * m1x + r11 * m1y + r12 * m1z);
    float tr_z = m2z - (r20 * m1x + r21 * m1y + r22 * m1z);

    // ---------- Phase C: residual norms (LDS re-read), 8 + 1 predicated ----------
    float lsum = 0.f;

#define RESJ(J) do {                                                     \
        int _j = (J);                                                    \
        float tx = pt[3 * _j + 0], ty = pt[3 * _j + 1], tz = pt[3 * _j + 2]; \
        float ax = tr_x + r00 * tx + r01 * ty + r02 * tz;                \
        float ay = tr_y + r10 * tx + r11 * ty + r12 * tz;                \
        float az = tr_z + r20 * tx + r21 * ty + r22 * tz;                \
        float dx = po[3 * _j + 0] - ax;                                  \
        float dy = po[3 * _j + 1] - ay;                                  \
        float dz = po[3 * _j + 2] - az;                                  \
        float d2 = fmaxf(dx * dx + dy * dy + dz * dz, 1e-30f);           \
        lsum += d2 * rsqrtf(d2);                                         \
    } while (0)

#pragma unroll 4
    for (int k = 0; k < 8; ++k) RESJ(q + 16 * k);
    if (q < KPT - 128) RESJ(q + 128);
#undef RESJ

#pragma unroll
    for (int o = 8; o > 0; o >>= 1) lsum += __shfl_xor_sync(0xffffffffu, lsum, o);
    if (!valid) lsum = 0.f;

    lsum += __shfl_xor_sync(0xffffffffu, lsum, 16);
    if (lane == 0)
        g_part[(size_t)blockIdx.x * 4 + warp] = (double)lsum;
}

__global__ void k_reduce1(int nparts)
{
    __shared__ double shd[8];
    int per = (nparts + RED1 - 1) / RED1;
    int lo  = blockIdx.x * per;
    int hi  = min(lo + per, nparts);
    double s = 0.0;
    for (int i = lo + threadIdx.x; i < hi; i += blockDim.x) s += g_part[i];
#pragma unroll
    for (int o = 16; o > 0; o >>= 1) s += __shfl_xor_sync(0xffffffffu, s, o);
    int wi = threadIdx.x >> 5, lane = threadIdx.x & 31;
    if (lane == 0) shd[wi] = s;
    __syncthreads();
    if (threadIdx.x < 32) {
        int nw = blockDim.x >> 5;
        double v = (threadIdx.x < nw) ? shd[threadIdx.x] : 0.0;
#pragma unroll
        for (int o = 4; o > 0; o >>= 1) v += __shfl_xor_sync(0xffffffffu, v, o);
        if (threadIdx.x == 0) g_part2[blockIdx.x] = v;
    }
}

__global__ void k_reduce2(float* __restrict__ out, double inv_cnt)
{
    double v = (threadIdx.x < RED1) ? g_part2[threadIdx.x] : 0.0;
#pragma unroll
    for (int o = 16; o > 0; o >>= 1) v += __shfl_xor_sync(0xffffffffu, v, o);
    if (threadIdx.x == 0) out[0] = (float)(v * inv_cnt);
}

extern "C" void kernel_launch(void* const* d_in, const int* in_sizes, int n_in,
                              void* d_out, int out_size)
{
    const float* g_output = (const float*)d_in[0];
    const float* g_target = (const float*)d_in[1];
    int n = in_sizes[0] / PTS3;

    size_t shbytes = (size_t)4 * WFLTS * sizeof(float);   // 25536 B per block
    cudaFuncSetAttribute(k_pa, cudaFuncAttributeMaxDynamicSharedMemorySize, (int)shbytes);

    int blocks = (n + SPB - 1) / SPB;
    k_pa<<<blocks, 128, shbytes>>>(g_output, g_target, n);
    k_reduce1<<<RED1, 256>>>(blocks * 4);
    double inv_cnt = 1.0 / ((double)n * (double)KPT);
    k_reduce2<<<1, 32>>>((float*)d_out, inv_cnt);
}